// round 13
// baseline (speedup 1.0000x reference)
#include <cuda_runtime.h>
#include <cstdint>

// S4D kernel generation as bf16 HMMA GEMMs.
//   l = 32u + v, u in [0,128), v in [0,32)
//   K[h,l] = sum_{m<64} F[u,m] * G[v,m]
// R13 = R10 + MMA dependency fix: the three split passes (Fh*Gh, Fh*Gl, Fl*Gh)
// were issued back-to-back into the SAME accumulator (RAW chain = HMMA latency
// exposed on every MMA). Reordered pass -> mt -> nt so same-acc reuse distance
// is 8 independent MMAs. Arithmetic identical to R10 (14.8us, rel 2.96e-5).

#define HN  1024
#define NM  32
#define LL  4096
#define TPB 64

__device__ __forceinline__ uint32_t pack_hi16(float a, float b) {
    uint32_t r;
    asm("prmt.b32 %0, %1, %2, 0x7632;"
        : "=r"(r) : "r"(__float_as_uint(a)), "r"(__float_as_uint(b)));
    return r;
}

__device__ __forceinline__ void mma16816(float* c, uint32_t a0, uint32_t a1,
                                         uint32_t a2, uint32_t a3,
                                         uint32_t b0, uint32_t b1) {
    asm volatile(
        "mma.sync.aligned.m16n8k16.row.col.f32.bf16.bf16.f32 "
        "{%0,%1,%2,%3}, {%4,%5,%6,%7}, {%8,%9}, {%0,%1,%2,%3};"
        : "+f"(c[0]), "+f"(c[1]), "+f"(c[2]), "+f"(c[3])
        : "r"(a0), "r"(a1), "r"(a2), "r"(a3), "r"(b0), "r"(b1));
}

struct Cx { float r, i; };
__device__ __forceinline__ Cx cmul(Cx a, Cx b) {
    return { a.r * b.r - a.i * b.i, a.r * b.i + a.i * b.r };
}
__device__ __forceinline__ Cx csq(Cx a) {
    return { a.r * a.r - a.i * a.i, 2.0f * a.r * a.i };
}

// B granule word index: reader granule (ks,h) at lane is one LDS.128.
#define BW(v, wc) (((wc) >> 2) * 128 + ((((v) & 7) << 2) + ((wc) & 3)) * 4 + ((v) >> 3))

__global__ void __launch_bounds__(TPB, 10)
s4d_hmma_kernel(const float* __restrict__ log_dt,      // (H)
                const float* __restrict__ C_real,      // (1,H,NM,2)
                const float* __restrict__ log_A_real,  // (H,NM)
                const float* __restrict__ A_imag,      // (H,NM)
                float* __restrict__ out)               // (1,H,L)
{
    __shared__ __align__(16) uint16_t sBh[2048], sBl[2048];  // 4 KB each
    __shared__ __align__(16) float2 T2c[16][34];             // Z^b, Z = dA^32
    __shared__ __align__(16) float2 Uc[4][34];               // 2*dC * Z16^a (this half)

    const int h    = blockIdx.x >> 1;
    const int half = blockIdx.x & 1;
    const int t    = threadIdx.x;
    const int wid  = t >> 5;
    const int lane = t & 31;

    // ---- Prologue: warp0 -> tables, warp1 -> B tile
    {
        const int m = lane;
        const float dt  = expf(log_dt[h]);
        const float Aor = -expf(log_A_real[h * NM + m]);
        const float Aoi = A_imag[h * NM + m];
        const float dtAr = Aor * dt, dtAi = Aoi * dt;
        const float denr = 1.0f - 0.5f * dtAr;
        const float deni = -0.5f * dtAi;
        const float inv  = 1.0f / (denr * denr + deni * deni);
        const float numr = 1.0f + 0.5f * dtAr;
        const float numi = 0.5f * dtAi;
        const Cx dA = { (numr * denr + numi * deni) * inv,
                        (numi * denr - numr * deni) * inv };

        if (wid == 1) {
            // B tile: G[v][m] = Re(dA^v), G[v][32+m] = -Im(dA^v); hi/lo split.
            const int wcR = m >> 1, wcI = 16 + (m >> 1), hw = m & 1;
            Cx w = {1.0f, 0.0f};
            #pragma unroll 1
            for (int v = 0; v < 32; ++v) {
                const int iR = (BW(v, wcR) << 1) + hw;
                const int iI = (BW(v, wcI) << 1) + hw;
                const uint32_t xr = __float_as_uint(w.r);
                const float hr = __uint_as_float(xr & 0xFFFF0000u);
                sBh[iR] = (uint16_t)(xr >> 16);
                sBl[iR] = (uint16_t)(__float_as_uint(w.r - hr) >> 16);
                const float niv = -w.i;
                const uint32_t xi = __float_as_uint(niv);
                const float hi = __uint_as_float(xi & 0xFFFF0000u);
                sBh[iI] = (uint16_t)(xi >> 16);
                sBl[iI] = (uint16_t)(__float_as_uint(niv - hi) >> 16);
                w = cmul(w, dA);
            }
        } else {
            const float Br = dt * denr * inv;
            const float Bi = -dt * deni * inv;
            const float Cr = C_real[(h * NM + m) * 2 + 0];
            const float Ci = C_real[(h * NM + m) * 2 + 1];
            const Cx dC = { 2.0f * (Cr * Br - Ci * Bi),     // factor 2 baked in
                            2.0f * (Cr * Bi + Ci * Br) };
            // Z = dA^32; T2[b] = Z^b
            Cx z = dA;
            #pragma unroll
            for (int j = 0; j < 5; ++j) z = csq(z);
            Cx p = {1.0f, 0.0f};
            #pragma unroll
            for (int b = 0; b < 16; ++b) {
                T2c[b][m] = make_float2(p.r, p.i);
                p = cmul(p, z);
            }
            const Cx z16 = p;                // dA^512
            // U rows for THIS half: start = dC * Z16^(4*half)
            Cx y = half ? cmul(dC, csq(csq(z16))) : dC;
            #pragma unroll
            for (int a = 0; a < 4; ++a) {
                Uc[a][m] = make_float2(y.r, y.i);
                y = cmul(y, z16);
            }
        }
    }
    __syncthreads();

    // ---- Mainloop: warp wid -> rows [64*half + 32*wid, +32)
    const int gid = lane >> 2;
    const int tig = lane & 3;

    float acc[2][4][4] = {};

    const float4* B4h = reinterpret_cast<const float4*>(sBh);
    const float4* B4l = reinterpret_cast<const float4*>(sBl);

    #pragma unroll
    for (int kq = 0; kq < 2; ++kq) {
        // modes for this thread: n0, n0+1, n0+8, n0+9
        const int n0 = 16 * kq + 2 * tig;

        const float4 tg01 = *reinterpret_cast<const float4*>(&T2c[gid][n0]);
        const float4 tg89 = *reinterpret_cast<const float4*>(&T2c[gid][n0 + 8]);
        const float4 th01 = *reinterpret_cast<const float4*>(&T2c[gid + 8][n0]);
        const float4 th89 = *reinterpret_cast<const float4*>(&T2c[gid + 8][n0 + 8]);
        const float tg_r[4] = { tg01.x, tg01.z, tg89.x, tg89.z };
        const float tg_i[4] = { tg01.y, tg01.w, tg89.y, tg89.w };
        const float th_r[4] = { th01.x, th01.z, th89.x, th89.z };
        const float th_i[4] = { th01.y, th01.w, th89.y, th89.w };

        // A fragments: [ksel(Re/Im)][hi/lo][mt][reg]
        uint32_t Af[2][2][2][4];
        #pragma unroll
        for (int mt = 0; mt < 2; ++mt) {
            const int aLoc = 2 * wid + mt;
            const float4 u01 = *reinterpret_cast<const float4*>(&Uc[aLoc][n0]);
            const float4 u89 = *reinterpret_cast<const float4*>(&Uc[aLoc][n0 + 8]);
            const float u_r[4] = { u01.x, u01.z, u89.x, u89.z };
            const float u_i[4] = { u01.y, u01.w, u89.y, u89.w };
            float pr0[4], pi0[4], pr1[4], pi1[4];
            #pragma unroll
            for (int j = 0; j < 4; ++j) {
                pr0[j] = u_r[j] * tg_r[j] - u_i[j] * tg_i[j];
                pi0[j] = u_r[j] * tg_i[j] + u_i[j] * tg_r[j];
                pr1[j] = u_r[j] * th_r[j] - u_i[j] * th_i[j];
                pi1[j] = u_r[j] * th_i[j] + u_i[j] * th_r[j];
            }
            #pragma unroll
            for (int cp = 0; cp < 2; ++cp) {
                const int j0 = cp * 2, j1 = cp * 2 + 1;
                Af[0][0][mt][cp * 2 + 0] = pack_hi16(pr0[j0], pr0[j1]);
                Af[0][0][mt][cp * 2 + 1] = pack_hi16(pr1[j0], pr1[j1]);
                Af[1][0][mt][cp * 2 + 0] = pack_hi16(pi0[j0], pi0[j1]);
                Af[1][0][mt][cp * 2 + 1] = pack_hi16(pi1[j0], pi1[j1]);
                const float d00 = pr0[j0] - __uint_as_float(__float_as_uint(pr0[j0]) & 0xFFFF0000u);
                const float d01 = pr0[j1] - __uint_as_float(__float_as_uint(pr0[j1]) & 0xFFFF0000u);
                const float d10 = pr1[j0] - __uint_as_float(__float_as_uint(pr1[j0]) & 0xFFFF0000u);
                const float d11 = pr1[j1] - __uint_as_float(__float_as_uint(pr1[j1]) & 0xFFFF0000u);
                Af[0][1][mt][cp * 2 + 0] = pack_hi16(d00, d01);
                Af[0][1][mt][cp * 2 + 1] = pack_hi16(d10, d11);
                const float e00 = pi0[j0] - __uint_as_float(__float_as_uint(pi0[j0]) & 0xFFFF0000u);
                const float e01 = pi0[j1] - __uint_as_float(__float_as_uint(pi0[j1]) & 0xFFFF0000u);
                const float e10 = pi1[j0] - __uint_as_float(__float_as_uint(pi1[j0]) & 0xFFFF0000u);
                const float e11 = pi1[j1] - __uint_as_float(__float_as_uint(pi1[j1]) & 0xFFFF0000u);
                Af[1][1][mt][cp * 2 + 0] = pack_hi16(e00, e01);
                Af[1][1][mt][cp * 2 + 1] = pack_hi16(e10, e11);
            }
        }

        // MMAs: ksel 0 -> ks=kq (Re cols), ksel 1 -> ks=kq+2 (Im cols).
        // Pass loop OUTSIDE mt/nt: same-acc reuse distance = 8 independent MMAs.
        #pragma unroll
        for (int ksel = 0; ksel < 2; ++ksel) {
            const int ks = kq + 2 * ksel;
            const float4 bh0 = B4h[(ks * 2 + 0) * 32 + lane];
            const float4 bh1 = B4h[(ks * 2 + 1) * 32 + lane];
            const float4 bl0 = B4l[(ks * 2 + 0) * 32 + lane];
            const float4 bl1 = B4l[(ks * 2 + 1) * 32 + lane];
            const uint32_t* h0 = reinterpret_cast<const uint32_t*>(&bh0);
            const uint32_t* h1 = reinterpret_cast<const uint32_t*>(&bh1);
            const uint32_t* l0 = reinterpret_cast<const uint32_t*>(&bl0);
            const uint32_t* l1 = reinterpret_cast<const uint32_t*>(&bl1);
            #pragma unroll
            for (int pass = 0; pass < 3; ++pass) {
                const uint32_t* b0 = (pass == 1) ? l0 : h0;   // pass1 = Fh*Gl
                const uint32_t* b1 = (pass == 1) ? l1 : h1;
                const int asel = (pass == 2) ? 1 : 0;          // pass2 = Fl*Gh
                #pragma unroll
                for (int mt = 0; mt < 2; ++mt) {
                    const uint32_t* aa = Af[ksel][asel][mt];
                    #pragma unroll
                    for (int nt = 0; nt < 4; ++nt)
                        mma16816(acc[mt][nt], aa[0], aa[1], aa[2], aa[3],
                                 b0[nt], b1[nt]);
                }
            }
        }
    }

    // ---- Epilogue
    float* __restrict__ o = out + (size_t)h * LL;
    const int r0 = 64 * half + 32 * wid;
    #pragma unroll
    for (int mt = 0; mt < 2; ++mt) {
        const int u0 = r0 + mt * 16 + gid;
        #pragma unroll
        for (int nt = 0; nt < 4; ++nt) {
            const int v = nt * 8 + tig * 2;
            *reinterpret_cast<float2*>(o + (size_t)u0 * 32 + v) =
                make_float2(acc[mt][nt][0], acc[mt][nt][1]);
            *reinterpret_cast<float2*>(o + (size_t)(u0 + 8) * 32 + v) =
                make_float2(acc[mt][nt][2], acc[mt][nt][3]);
        }
    }
}

extern "C" void kernel_launch(void* const* d_in, const int* in_sizes, int n_in,
                              void* d_out, int out_size) {
    const float* log_dt     = (const float*)d_in[0];
    const float* C_real     = (const float*)d_in[1];
    const float* log_A_real = (const float*)d_in[2];
    const float* A_imag     = (const float*)d_in[3];
    float* out = (float*)d_out;
    s4d_hmma_kernel<<<HN * 2, TPB>>>(log_dt, C_real, log_A_real, A_imag, out);
}

// round 14
// speedup vs baseline: 1.3814x; 1.3814x over previous
#include <cuda_runtime.h>
#include <cstdint>

// S4D kernel generation as bf16 HMMA GEMMs.
//   l = 32u + v, u in [0,128), v in [0,32)
//   K[h,l] = sum_{m<64} F[u,m] * G[v,m]
// R14 = R10 (best, 14.8us) + packed-f32x2 A-fragment construction:
//   tables stored pre-duplicated: T2p[b][m]=(r,r,i,i), Up[a][m]=(ur,ui,-ui,ur)
//   product (pr,pi) = fma2((ti,ti),(-ui,ur), mul2((tr,tr),(ur,ui)))  [2 ops vs 4]
//   lo-split via LOP3 negtrunc + one add2 per product                [3 ops vs 4]
// MMA ordering/epilogue byte-identical to R10 (R13 reorder regressed; reverted).

#define HN  1024
#define NM  32
#define LL  4096
#define TPB 64

typedef unsigned long long u64;

__device__ __forceinline__ u64 mul2(u64 a, u64 b) {
    u64 d; asm("mul.rn.f32x2 %0, %1, %2;" : "=l"(d) : "l"(a), "l"(b)); return d;
}
__device__ __forceinline__ u64 fma2(u64 a, u64 b, u64 c) {
    u64 d; asm("fma.rn.f32x2 %0, %1, %2, %3;" : "=l"(d) : "l"(a), "l"(b), "l"(c)); return d;
}
__device__ __forceinline__ u64 add2(u64 a, u64 b) {
    u64 d; asm("add.rn.f32x2 %0, %1, %2;" : "=l"(d) : "l"(a), "l"(b)); return d;
}
__device__ __forceinline__ void unpk(u64 v, uint32_t& l, uint32_t& h) {
    asm("mov.b64 {%0,%1}, %2;" : "=r"(l), "=r"(h) : "l"(v));
}
__device__ __forceinline__ u64 pk(uint32_t l, uint32_t h) {
    u64 v; asm("mov.b64 %0, {%1,%2};" : "=l"(v) : "r"(l), "r"(h)); return v;
}
// packed negated bf16-truncation: per half (p & 0xFFFF0000) ^ 0x80000000
__device__ __forceinline__ u64 negtrunc2(u64 p) {
    uint32_t l, h; unpk(p, l, h);
    return pk((l & 0xFFFF0000u) ^ 0x80000000u, (h & 0xFFFF0000u) ^ 0x80000000u);
}

__device__ __forceinline__ uint32_t pack_hi16(uint32_t a, uint32_t b) {
    uint32_t r;
    asm("prmt.b32 %0, %1, %2, 0x7632;" : "=r"(r) : "r"(a), "r"(b));
    return r;
}

__device__ __forceinline__ void mma16816(float* c, uint32_t a0, uint32_t a1,
                                         uint32_t a2, uint32_t a3,
                                         uint32_t b0, uint32_t b1) {
    asm volatile(
        "mma.sync.aligned.m16n8k16.row.col.f32.bf16.bf16.f32 "
        "{%0,%1,%2,%3}, {%4,%5,%6,%7}, {%8,%9}, {%0,%1,%2,%3};"
        : "+f"(c[0]), "+f"(c[1]), "+f"(c[2]), "+f"(c[3])
        : "r"(a0), "r"(a1), "r"(a2), "r"(a3), "r"(b0), "r"(b1));
}

struct Cx { float r, i; };
__device__ __forceinline__ Cx cmul(Cx a, Cx b) {
    return { a.r * b.r - a.i * b.i, a.r * b.i + a.i * b.r };
}
__device__ __forceinline__ Cx csq(Cx a) {
    return { a.r * a.r - a.i * a.i, 2.0f * a.r * a.i };
}

// B granule word index: reader granule (ks,h) at lane is one LDS.128.
#define BW(v, wc) (((wc) >> 2) * 128 + ((((v) & 7) << 2) + ((wc) & 3)) * 4 + ((v) >> 3))

__global__ void __launch_bounds__(TPB, 10)
s4d_hmma_kernel(const float* __restrict__ log_dt,      // (H)
                const float* __restrict__ C_real,      // (1,H,NM,2)
                const float* __restrict__ log_A_real,  // (H,NM)
                const float* __restrict__ A_imag,      // (H,NM)
                float* __restrict__ out)               // (1,H,L)
{
    __shared__ __align__(16) uint16_t sBh[2048], sBl[2048];  // 4 KB each
    __shared__ __align__(16) float4 T2p[16][NM];             // (r,r,i,i): Z^b, Z=dA^32 (8 KB)
    __shared__ __align__(16) float4 Up[4][NM];               // (ur,ui,-ui,ur): 2*dC*Z16^a (2 KB)

    const int h    = blockIdx.x >> 1;
    const int half = blockIdx.x & 1;
    const int t    = threadIdx.x;
    const int wid  = t >> 5;
    const int lane = t & 31;

    // ---- Prologue: warp0 -> tables, warp1 -> B tile
    {
        const int m = lane;
        const float dt  = expf(log_dt[h]);
        const float Aor = -expf(log_A_real[h * NM + m]);
        const float Aoi = A_imag[h * NM + m];
        const float dtAr = Aor * dt, dtAi = Aoi * dt;
        const float denr = 1.0f - 0.5f * dtAr;
        const float deni = -0.5f * dtAi;
        const float inv  = 1.0f / (denr * denr + deni * deni);
        const float numr = 1.0f + 0.5f * dtAr;
        const float numi = 0.5f * dtAi;
        const Cx dA = { (numr * denr + numi * deni) * inv,
                        (numi * denr - numr * deni) * inv };

        if (wid == 1) {
            // B tile: G[v][m] = Re(dA^v), G[v][32+m] = -Im(dA^v); hi/lo split.
            const int wcR = m >> 1, wcI = 16 + (m >> 1), hw = m & 1;
            Cx w = {1.0f, 0.0f};
            #pragma unroll 1
            for (int v = 0; v < 32; ++v) {
                const int iR = (BW(v, wcR) << 1) + hw;
                const int iI = (BW(v, wcI) << 1) + hw;
                const uint32_t xr = __float_as_uint(w.r);
                const float hr = __uint_as_float(xr & 0xFFFF0000u);
                sBh[iR] = (uint16_t)(xr >> 16);
                sBl[iR] = (uint16_t)(__float_as_uint(w.r - hr) >> 16);
                const float niv = -w.i;
                const uint32_t xi = __float_as_uint(niv);
                const float hi = __uint_as_float(xi & 0xFFFF0000u);
                sBh[iI] = (uint16_t)(xi >> 16);
                sBl[iI] = (uint16_t)(__float_as_uint(niv - hi) >> 16);
                w = cmul(w, dA);
            }
        } else {
            const float Br = dt * denr * inv;
            const float Bi = -dt * deni * inv;
            const float Cr = C_real[(h * NM + m) * 2 + 0];
            const float Ci = C_real[(h * NM + m) * 2 + 1];
            const Cx dC = { 2.0f * (Cr * Br - Ci * Bi),     // factor 2 baked in
                            2.0f * (Cr * Bi + Ci * Br) };
            // Z = dA^32; T2[b] = Z^b, stored duplicated (r,r,i,i)
            Cx z = dA;
            #pragma unroll
            for (int j = 0; j < 5; ++j) z = csq(z);
            Cx p = {1.0f, 0.0f};
            #pragma unroll
            for (int b = 0; b < 16; ++b) {
                T2p[b][m] = make_float4(p.r, p.r, p.i, p.i);
                p = cmul(p, z);
            }
            const Cx z16 = p;                // dA^512
            // U rows for THIS half: start = dC * Z16^(4*half); store (ur,ui,-ui,ur)
            Cx y = half ? cmul(dC, csq(csq(z16))) : dC;
            #pragma unroll
            for (int a = 0; a < 4; ++a) {
                Up[a][m] = make_float4(y.r, y.i, -y.i, y.r);
                y = cmul(y, z16);
            }
        }
    }
    __syncthreads();

    // ---- Mainloop: warp wid -> rows [64*half + 32*wid, +32)
    const int gid = lane >> 2;
    const int tig = lane & 3;

    float acc[2][4][4] = {};

    const float4* B4h = reinterpret_cast<const float4*>(sBh);
    const float4* B4l = reinterpret_cast<const float4*>(sBl);

    #pragma unroll
    for (int kq = 0; kq < 2; ++kq) {
        // modes for this thread: n0, n0+1, n0+8, n0+9
        const int n0 = 16 * kq + 2 * tig;

        // T2 rows gid (g) and gid+8 (h): per mode one ulonglong2 {(r,r),(i,i)}
        ulonglong2 tg[4], th[4];
        #pragma unroll
        for (int j = 0; j < 4; ++j) {
            const int n = n0 + (j >> 1) * 8 + (j & 1);
            tg[j] = *reinterpret_cast<const ulonglong2*>(&T2p[gid][n]);
            th[j] = *reinterpret_cast<const ulonglong2*>(&T2p[gid + 8][n]);
        }

        // A fragments: [ksel(Re/Im)][hi/lo][mt][reg]
        uint32_t Af[2][2][2][4];
        #pragma unroll
        for (int mt = 0; mt < 2; ++mt) {
            const int aLoc = 2 * wid + mt;
            u64 Pg[4], Ph[4];
            #pragma unroll
            for (int j = 0; j < 4; ++j) {
                const int n = n0 + (j >> 1) * 8 + (j & 1);
                const ulonglong2 uu = *reinterpret_cast<const ulonglong2*>(&Up[aLoc][n]);
                Pg[j] = fma2(tg[j].y, uu.y, mul2(tg[j].x, uu.x));   // (pr, pi) row gid
                Ph[j] = fma2(th[j].y, uu.y, mul2(th[j].x, uu.x));   // (pr, pi) row gid+8
            }
            // hi fragments straight from P (truncation = top 16 bits)
            uint32_t g_lo[4], g_hi[4], h_lo[4], h_hi[4];
            #pragma unroll
            for (int j = 0; j < 4; ++j) {
                unpk(Pg[j], g_lo[j], g_hi[j]);
                unpk(Ph[j], h_lo[j], h_hi[j]);
            }
            Af[0][0][mt][0] = pack_hi16(g_lo[0], g_lo[1]);
            Af[0][0][mt][1] = pack_hi16(h_lo[0], h_lo[1]);
            Af[0][0][mt][2] = pack_hi16(g_lo[2], g_lo[3]);
            Af[0][0][mt][3] = pack_hi16(h_lo[2], h_lo[3]);
            Af[1][0][mt][0] = pack_hi16(g_hi[0], g_hi[1]);
            Af[1][0][mt][1] = pack_hi16(h_hi[0], h_hi[1]);
            Af[1][0][mt][2] = pack_hi16(g_hi[2], g_hi[3]);
            Af[1][0][mt][3] = pack_hi16(h_hi[2], h_hi[3]);
            // lo fragments: L = P - trunc(P) via packed add of negated truncation
            uint32_t lg_lo[4], lg_hi[4], lh_lo[4], lh_hi[4];
            #pragma unroll
            for (int j = 0; j < 4; ++j) {
                const u64 Lg = add2(Pg[j], negtrunc2(Pg[j]));
                const u64 Lh = add2(Ph[j], negtrunc2(Ph[j]));
                unpk(Lg, lg_lo[j], lg_hi[j]);
                unpk(Lh, lh_lo[j], lh_hi[j]);
            }
            Af[0][1][mt][0] = pack_hi16(lg_lo[0], lg_lo[1]);
            Af[0][1][mt][1] = pack_hi16(lh_lo[0], lh_lo[1]);
            Af[0][1][mt][2] = pack_hi16(lg_lo[2], lg_lo[3]);
            Af[0][1][mt][3] = pack_hi16(lh_lo[2], lh_lo[3]);
            Af[1][1][mt][0] = pack_hi16(lg_hi[0], lg_hi[1]);
            Af[1][1][mt][1] = pack_hi16(lh_hi[0], lh_hi[1]);
            Af[1][1][mt][2] = pack_hi16(lg_hi[2], lg_hi[3]);
            Af[1][1][mt][3] = pack_hi16(lh_hi[2], lh_hi[3]);
        }

        // MMAs (R10 ordering): ksel 0 -> ks=kq (Re), ksel 1 -> ks=kq+2 (Im)
        #pragma unroll
        for (int ksel = 0; ksel < 2; ++ksel) {
            const int ks = kq + 2 * ksel;
            const float4 bh0 = B4h[(ks * 2 + 0) * 32 + lane];
            const float4 bh1 = B4h[(ks * 2 + 1) * 32 + lane];
            const float4 bl0 = B4l[(ks * 2 + 0) * 32 + lane];
            const float4 bl1 = B4l[(ks * 2 + 1) * 32 + lane];
            const uint32_t* h0 = reinterpret_cast<const uint32_t*>(&bh0);
            const uint32_t* h1 = reinterpret_cast<const uint32_t*>(&bh1);
            const uint32_t* l0 = reinterpret_cast<const uint32_t*>(&bl0);
            const uint32_t* l1 = reinterpret_cast<const uint32_t*>(&bl1);
            #pragma unroll
            for (int mt = 0; mt < 2; ++mt) {
                const uint32_t* ah = Af[ksel][0][mt];
                const uint32_t* al = Af[ksel][1][mt];
                #pragma unroll
                for (int nt = 0; nt < 4; ++nt) {
                    mma16816(acc[mt][nt], ah[0], ah[1], ah[2], ah[3], h0[nt], h1[nt]); // Fh*Gh
                    mma16816(acc[mt][nt], ah[0], ah[1], ah[2], ah[3], l0[nt], l1[nt]); // Fh*Gl
                    mma16816(acc[mt][nt], al[0], al[1], al[2], al[3], h0[nt], h1[nt]); // Fl*Gh
                }
            }
        }
    }

    // ---- Epilogue
    float* __restrict__ o = out + (size_t)h * LL;
    const int r0 = 64 * half + 32 * wid;
    #pragma unroll
    for (int mt = 0; mt < 2; ++mt) {
        const int u0 = r0 + mt * 16 + gid;
        #pragma unroll
        for (int nt = 0; nt < 4; ++nt) {
            const int v = nt * 8 + tig * 2;
            *reinterpret_cast<float2*>(o + (size_t)u0 * 32 + v) =
                make_float2(acc[mt][nt][0], acc[mt][nt][1]);
            *reinterpret_cast<float2*>(o + (size_t)(u0 + 8) * 32 + v) =
                make_float2(acc[mt][nt][2], acc[mt][nt][3]);
        }
    }
}

extern "C" void kernel_launch(void* const* d_in, const int* in_sizes, int n_in,
                              void* d_out, int out_size) {
    const float* log_dt     = (const float*)d_in[0];
    const float* C_real     = (const float*)d_in[1];
    const float* log_A_real = (const float*)d_in[2];
    const float* A_imag     = (const float*)d_in[3];
    float* out = (float*)d_out;
    s4d_hmma_kernel<<<HN * 2, TPB>>>(log_dt, C_real, log_A_real, A_imag, out);
}

// round 15
// speedup vs baseline: 1.5489x; 1.1213x over previous
#include <cuda_runtime.h>
#include <cstdint>

// S4D kernel generation as bf16 HMMA GEMMs — FINAL (lock-in of R10, best: 14.8us).
//   l = 32u + v, u in [0,128), v in [0,32)
//   K[h,l] = sum_{m<64} F[u,m] * G[v,m]
//     F[u,n] = Re(2 dC_n dA_n^{32u}),  F[u,32+n] = Im(...)
//     G[v,n] = Re(dA_n^v),             G[v,32+n] = -Im(dA_n^v)
// Design: CTA = half channel (TPB=64, grid 2048, 10 CTAs/SM). Warp0 builds
// power tables (Z=dA^32 ladder), warp1 builds the B tile in lane-linear 16B
// granules (every mainloop B load = one LDS.128). A fragments are computed in
// registers by the consuming thread (no A smem round-trip). Precision: 2-term
// bf16 truncation split, 3 MMA passes (Fh*Gh + Fh*Gl + Fl*Gh), rel_err 2.96e-5.
// Falsified alternatives (kept for the record): +occupancy (R10->13/SM), LDS
// conflict-free tables (R11), warp-specialized prologue (R12), MMA pass
// reorder (R13), packed f32x2 fragment math (R14) — all neutral or regressions.

#define HN  1024
#define NM  32
#define LL  4096
#define TPB 64

__device__ __forceinline__ uint32_t pack_hi16(float a, float b) {
    uint32_t r;
    asm("prmt.b32 %0, %1, %2, 0x7632;"
        : "=r"(r) : "r"(__float_as_uint(a)), "r"(__float_as_uint(b)));
    return r;
}

__device__ __forceinline__ void mma16816(float* c, uint32_t a0, uint32_t a1,
                                         uint32_t a2, uint32_t a3,
                                         uint32_t b0, uint32_t b1) {
    asm volatile(
        "mma.sync.aligned.m16n8k16.row.col.f32.bf16.bf16.f32 "
        "{%0,%1,%2,%3}, {%4,%5,%6,%7}, {%8,%9}, {%0,%1,%2,%3};"
        : "+f"(c[0]), "+f"(c[1]), "+f"(c[2]), "+f"(c[3])
        : "r"(a0), "r"(a1), "r"(a2), "r"(a3), "r"(b0), "r"(b1));
}

struct Cx { float r, i; };
__device__ __forceinline__ Cx cmul(Cx a, Cx b) {
    return { a.r * b.r - a.i * b.i, a.r * b.i + a.i * b.r };
}
__device__ __forceinline__ Cx csq(Cx a) {
    return { a.r * a.r - a.i * a.i, 2.0f * a.r * a.i };
}

// B granule word index: reader granule (ks,h) at lane is one LDS.128.
#define BW(v, wc) (((wc) >> 2) * 128 + ((((v) & 7) << 2) + ((wc) & 3)) * 4 + ((v) >> 3))

__global__ void __launch_bounds__(TPB, 10)
s4d_hmma_kernel(const float* __restrict__ log_dt,      // (H)
                const float* __restrict__ C_real,      // (1,H,NM,2)
                const float* __restrict__ log_A_real,  // (H,NM)
                const float* __restrict__ A_imag,      // (H,NM)
                float* __restrict__ out)               // (1,H,L)
{
    __shared__ __align__(16) uint16_t sBh[2048], sBl[2048];  // 4 KB each
    __shared__ __align__(16) float2 T2c[16][34];             // Z^b, Z = dA^32
    __shared__ __align__(16) float2 Uc[4][34];               // 2*dC * Z16^a (this half)

    const int h    = blockIdx.x >> 1;
    const int half = blockIdx.x & 1;
    const int t    = threadIdx.x;
    const int wid  = t >> 5;
    const int lane = t & 31;

    // ---- Prologue: warp0 -> tables, warp1 -> B tile
    {
        const int m = lane;
        const float dt  = expf(log_dt[h]);
        const float Aor = -expf(log_A_real[h * NM + m]);
        const float Aoi = A_imag[h * NM + m];
        const float dtAr = Aor * dt, dtAi = Aoi * dt;
        const float denr = 1.0f - 0.5f * dtAr;
        const float deni = -0.5f * dtAi;
        const float inv  = 1.0f / (denr * denr + deni * deni);
        const float numr = 1.0f + 0.5f * dtAr;
        const float numi = 0.5f * dtAi;
        const Cx dA = { (numr * denr + numi * deni) * inv,
                        (numi * denr - numr * deni) * inv };

        if (wid == 1) {
            // B tile: G[v][m] = Re(dA^v), G[v][32+m] = -Im(dA^v); hi/lo split.
            const int wcR = m >> 1, wcI = 16 + (m >> 1), hw = m & 1;
            Cx w = {1.0f, 0.0f};
            #pragma unroll 1
            for (int v = 0; v < 32; ++v) {
                const int iR = (BW(v, wcR) << 1) + hw;
                const int iI = (BW(v, wcI) << 1) + hw;
                const uint32_t xr = __float_as_uint(w.r);
                const float hr = __uint_as_float(xr & 0xFFFF0000u);
                sBh[iR] = (uint16_t)(xr >> 16);
                sBl[iR] = (uint16_t)(__float_as_uint(w.r - hr) >> 16);
                const float niv = -w.i;
                const uint32_t xi = __float_as_uint(niv);
                const float hi = __uint_as_float(xi & 0xFFFF0000u);
                sBh[iI] = (uint16_t)(xi >> 16);
                sBl[iI] = (uint16_t)(__float_as_uint(niv - hi) >> 16);
                w = cmul(w, dA);
            }
        } else {
            const float Br = dt * denr * inv;
            const float Bi = -dt * deni * inv;
            const float Cr = C_real[(h * NM + m) * 2 + 0];
            const float Ci = C_real[(h * NM + m) * 2 + 1];
            const Cx dC = { 2.0f * (Cr * Br - Ci * Bi),     // factor 2 baked in
                            2.0f * (Cr * Bi + Ci * Br) };
            // Z = dA^32; T2[b] = Z^b
            Cx z = dA;
            #pragma unroll
            for (int j = 0; j < 5; ++j) z = csq(z);
            Cx p = {1.0f, 0.0f};
            #pragma unroll
            for (int b = 0; b < 16; ++b) {
                T2c[b][m] = make_float2(p.r, p.i);
                p = cmul(p, z);
            }
            const Cx z16 = p;                // dA^512
            // U rows for THIS half: start = dC * Z16^(4*half)
            Cx y = half ? cmul(dC, csq(csq(z16))) : dC;
            #pragma unroll
            for (int a = 0; a < 4; ++a) {
                Uc[a][m] = make_float2(y.r, y.i);
                y = cmul(y, z16);
            }
        }
    }
    __syncthreads();

    // ---- Mainloop: warp wid -> rows [64*half + 32*wid, +32)
    const int gid = lane >> 2;
    const int tig = lane & 3;

    float acc[2][4][4] = {};

    const float4* B4h = reinterpret_cast<const float4*>(sBh);
    const float4* B4l = reinterpret_cast<const float4*>(sBl);

    #pragma unroll
    for (int kq = 0; kq < 2; ++kq) {
        // modes for this thread: n0, n0+1, n0+8, n0+9
        const int n0 = 16 * kq + 2 * tig;

        const float4 tg01 = *reinterpret_cast<const float4*>(&T2c[gid][n0]);
        const float4 tg89 = *reinterpret_cast<const float4*>(&T2c[gid][n0 + 8]);
        const float4 th01 = *reinterpret_cast<const float4*>(&T2c[gid + 8][n0]);
        const float4 th89 = *reinterpret_cast<const float4*>(&T2c[gid + 8][n0 + 8]);
        const float tg_r[4] = { tg01.x, tg01.z, tg89.x, tg89.z };
        const float tg_i[4] = { tg01.y, tg01.w, tg89.y, tg89.w };
        const float th_r[4] = { th01.x, th01.z, th89.x, th89.z };
        const float th_i[4] = { th01.y, th01.w, th89.y, th89.w };

        // A fragments: [ksel(Re/Im)][hi/lo][mt][reg]
        uint32_t Af[2][2][2][4];
        #pragma unroll
        for (int mt = 0; mt < 2; ++mt) {
            const int aLoc = 2 * wid + mt;
            const float4 u01 = *reinterpret_cast<const float4*>(&Uc[aLoc][n0]);
            const float4 u89 = *reinterpret_cast<const float4*>(&Uc[aLoc][n0 + 8]);
            const float u_r[4] = { u01.x, u01.z, u89.x, u89.z };
            const float u_i[4] = { u01.y, u01.w, u89.y, u89.w };
            float pr0[4], pi0[4], pr1[4], pi1[4];
            #pragma unroll
            for (int j = 0; j < 4; ++j) {
                pr0[j] = u_r[j] * tg_r[j] - u_i[j] * tg_i[j];
                pi0[j] = u_r[j] * tg_i[j] + u_i[j] * tg_r[j];
                pr1[j] = u_r[j] * th_r[j] - u_i[j] * th_i[j];
                pi1[j] = u_r[j] * th_i[j] + u_i[j] * th_r[j];
            }
            #pragma unroll
            for (int cp = 0; cp < 2; ++cp) {
                const int j0 = cp * 2, j1 = cp * 2 + 1;
                Af[0][0][mt][cp * 2 + 0] = pack_hi16(pr0[j0], pr0[j1]);
                Af[0][0][mt][cp * 2 + 1] = pack_hi16(pr1[j0], pr1[j1]);
                Af[1][0][mt][cp * 2 + 0] = pack_hi16(pi0[j0], pi0[j1]);
                Af[1][0][mt][cp * 2 + 1] = pack_hi16(pi1[j0], pi1[j1]);
                const float d00 = pr0[j0] - __uint_as_float(__float_as_uint(pr0[j0]) & 0xFFFF0000u);
                const float d01 = pr0[j1] - __uint_as_float(__float_as_uint(pr0[j1]) & 0xFFFF0000u);
                const float d10 = pr1[j0] - __uint_as_float(__float_as_uint(pr1[j0]) & 0xFFFF0000u);
                const float d11 = pr1[j1] - __uint_as_float(__float_as_uint(pr1[j1]) & 0xFFFF0000u);
                Af[0][1][mt][cp * 2 + 0] = pack_hi16(d00, d01);
                Af[0][1][mt][cp * 2 + 1] = pack_hi16(d10, d11);
                const float e00 = pi0[j0] - __uint_as_float(__float_as_uint(pi0[j0]) & 0xFFFF0000u);
                const float e01 = pi0[j1] - __uint_as_float(__float_as_uint(pi0[j1]) & 0xFFFF0000u);
                const float e10 = pi1[j0] - __uint_as_float(__float_as_uint(pi1[j0]) & 0xFFFF0000u);
                const float e11 = pi1[j1] - __uint_as_float(__float_as_uint(pi1[j1]) & 0xFFFF0000u);
                Af[1][1][mt][cp * 2 + 0] = pack_hi16(e00, e01);
                Af[1][1][mt][cp * 2 + 1] = pack_hi16(e10, e11);
            }
        }

        // MMAs: ksel 0 -> ks=kq (Re cols), ksel 1 -> ks=kq+2 (Im cols)
        #pragma unroll
        for (int ksel = 0; ksel < 2; ++ksel) {
            const int ks = kq + 2 * ksel;
            const float4 bh0 = B4h[(ks * 2 + 0) * 32 + lane];
            const float4 bh1 = B4h[(ks * 2 + 1) * 32 + lane];
            const float4 bl0 = B4l[(ks * 2 + 0) * 32 + lane];
            const float4 bl1 = B4l[(ks * 2 + 1) * 32 + lane];
            const uint32_t* h0 = reinterpret_cast<const uint32_t*>(&bh0);
            const uint32_t* h1 = reinterpret_cast<const uint32_t*>(&bh1);
            const uint32_t* l0 = reinterpret_cast<const uint32_t*>(&bl0);
            const uint32_t* l1 = reinterpret_cast<const uint32_t*>(&bl1);
            #pragma unroll
            for (int mt = 0; mt < 2; ++mt) {
                const uint32_t* ah = Af[ksel][0][mt];
                const uint32_t* al = Af[ksel][1][mt];
                #pragma unroll
                for (int nt = 0; nt < 4; ++nt) {
                    mma16816(acc[mt][nt], ah[0], ah[1], ah[2], ah[3], h0[nt], h1[nt]); // Fh*Gh
                    mma16816(acc[mt][nt], ah[0], ah[1], ah[2], ah[3], l0[nt], l1[nt]); // Fh*Gl
                    mma16816(acc[mt][nt], al[0], al[1], al[2], al[3], h0[nt], h1[nt]); // Fl*Gh
                }
            }
        }
    }

    // ---- Epilogue
    float* __restrict__ o = out + (size_t)h * LL;
    const int r0 = 64 * half + 32 * wid;
    #pragma unroll
    for (int mt = 0; mt < 2; ++mt) {
        const int u0 = r0 + mt * 16 + gid;
        #pragma unroll
        for (int nt = 0; nt < 4; ++nt) {
            const int v = nt * 8 + tig * 2;
            *reinterpret_cast<float2*>(o + (size_t)u0 * 32 + v) =
                make_float2(acc[mt][nt][0], acc[mt][nt][1]);
            *reinterpret_cast<float2*>(o + (size_t)(u0 + 8) * 32 + v) =
                make_float2(acc[mt][nt][2], acc[mt][nt][3]);
        }
    }
}

extern "C" void kernel_launch(void* const* d_in, const int* in_sizes, int n_in,
                              void* d_out, int out_size) {
    const float* log_dt     = (const float*)d_in[0];
    const float* C_real     = (const float*)d_in[1];
    const float* log_A_real = (const float*)d_in[2];
    const float* A_imag     = (const float*)d_in[3];
    float* out = (float*)d_out;
    s4d_hmma_kernel<<<HN * 2, TPB>>>(log_dt, C_real, log_A_real, A_imag, out);
}

// round 16
// speedup vs baseline: 1.5758x; 1.0173x over previous
#include <cuda_runtime.h>
#include <cstdint>

// S4D kernel generation as bf16 HMMA GEMMs.
//   l = 32u + v, u in [0,128), v in [0,32)
//   K[h,l] = sum_{m<64} F[u,m] * G[v,m]
// R16 = R10 mainloop (best, 14.8us) + rebuilt prologue:
//   B[v][m] = dA^(8a) * dA^b via register ladder tb[0..7] (chain depth ~4) --
//   replaces warp1's 32-step serial recurrence (~830 dyn instrs, 32-cmul chain).
//   Warps balanced: warp1 fills v[0,20), warp0 fills v[20,32) after T2/U.
//   Full unroll => swizzle addresses constant-fold. Grid/TPB/occupancy/mainloop
//   identical to R10.

#define HN  1024
#define NM  32
#define LL  4096
#define TPB 64

__device__ __forceinline__ uint32_t pack_hi16(float a, float b) {
    uint32_t r;
    asm("prmt.b32 %0, %1, %2, 0x7632;"
        : "=r"(r) : "r"(__float_as_uint(a)), "r"(__float_as_uint(b)));
    return r;
}

__device__ __forceinline__ void mma16816(float* c, uint32_t a0, uint32_t a1,
                                         uint32_t a2, uint32_t a3,
                                         uint32_t b0, uint32_t b1) {
    asm volatile(
        "mma.sync.aligned.m16n8k16.row.col.f32.bf16.bf16.f32 "
        "{%0,%1,%2,%3}, {%4,%5,%6,%7}, {%8,%9}, {%0,%1,%2,%3};"
        : "+f"(c[0]), "+f"(c[1]), "+f"(c[2]), "+f"(c[3])
        : "r"(a0), "r"(a1), "r"(a2), "r"(a3), "r"(b0), "r"(b1));
}

struct Cx { float r, i; };
__device__ __forceinline__ Cx cmul(Cx a, Cx b) {
    return { a.r * b.r - a.i * b.i, a.r * b.i + a.i * b.r };
}
__device__ __forceinline__ Cx csq(Cx a) {
    return { a.r * a.r - a.i * a.i, 2.0f * a.r * a.i };
}

// B granule word index: reader granule (ks,h) at lane is one LDS.128.
#define BW(v, wc) (((wc) >> 2) * 128 + ((((v) & 7) << 2) + ((wc) & 3)) * 4 + ((v) >> 3))

// Store one complex B entry (hi/lo truncation split) at compile-time v.
__device__ __forceinline__ void emitB(uint16_t* sBh, uint16_t* sBl,
                                      int v, int wcR, int wcI, int hw, Cx w) {
    const int iR = (BW(v, wcR) << 1) + hw;
    const int iI = (BW(v, wcI) << 1) + hw;
    const uint32_t xr = __float_as_uint(w.r);
    const float hr = __uint_as_float(xr & 0xFFFF0000u);
    sBh[iR] = (uint16_t)(xr >> 16);
    sBl[iR] = (uint16_t)(__float_as_uint(w.r - hr) >> 16);
    const float niv = -w.i;
    const uint32_t xi = __float_as_uint(niv);
    const float hi = __uint_as_float(xi & 0xFFFF0000u);
    sBh[iI] = (uint16_t)(xi >> 16);
    sBl[iI] = (uint16_t)(__float_as_uint(niv - hi) >> 16);
}

__global__ void __launch_bounds__(TPB, 10)
s4d_hmma_kernel(const float* __restrict__ log_dt,      // (H)
                const float* __restrict__ C_real,      // (1,H,NM,2)
                const float* __restrict__ log_A_real,  // (H,NM)
                const float* __restrict__ A_imag,      // (H,NM)
                float* __restrict__ out)               // (1,H,L)
{
    __shared__ __align__(16) uint16_t sBh[2048], sBl[2048];  // 4 KB each
    __shared__ __align__(16) float2 T2c[16][34];             // Z^b, Z = dA^32
    __shared__ __align__(16) float2 Uc[4][34];               // 2*dC * Z16^a (this half)

    const int h    = blockIdx.x >> 1;
    const int half = blockIdx.x & 1;
    const int t    = threadIdx.x;
    const int wid  = t >> 5;
    const int lane = t & 31;

    // ---- Prologue: shared power ladder, then warp-balanced fills
    {
        const int m = lane;
        const float dt  = expf(log_dt[h]);
        const float Aor = -expf(log_A_real[h * NM + m]);
        const float Aoi = A_imag[h * NM + m];
        const float dtAr = Aor * dt, dtAi = Aoi * dt;
        const float denr = 1.0f - 0.5f * dtAr;
        const float deni = -0.5f * dtAi;
        const float inv  = 1.0f / (denr * denr + deni * deni);
        const float numr = 1.0f + 0.5f * dtAr;
        const float numi = 0.5f * dtAi;
        const Cx dA = { (numr * denr + numi * deni) * inv,
                        (numi * denr - numr * deni) * inv };

        // tb[b] = dA^b via short chains (depth ~4)
        const Cx d2 = csq(dA);
        const Cx d4 = csq(d2);
        const Cx d8 = csq(d4);
        Cx tb[8];
        tb[0] = Cx{1.0f, 0.0f};
        tb[1] = dA;
        tb[2] = d2;
        tb[3] = cmul(d2, dA);
        tb[4] = d4;
        tb[5] = cmul(d4, dA);
        tb[6] = cmul(d4, d2);
        tb[7] = cmul(d4, tb[3]);
        const Cx ta2 = csq(d8);          // dA^16

        const int wcR = m >> 1, wcI = 16 + (m >> 1), hw = m & 1;

        if (wid == 1) {
            // B rows v in [0,20)
            #pragma unroll
            for (int v = 0; v < 8; ++v)
                emitB(sBh, sBl, v, wcR, wcI, hw, tb[v]);
            #pragma unroll
            for (int v = 8; v < 16; ++v)
                emitB(sBh, sBl, v, wcR, wcI, hw, cmul(d8, tb[v - 8]));
            #pragma unroll
            for (int v = 16; v < 20; ++v)
                emitB(sBh, sBl, v, wcR, wcI, hw, cmul(ta2, tb[v - 16]));
        } else {
            // T2 table: Z = dA^32 = (dA^16)^2
            const Cx Z = csq(ta2);
            Cx p = {1.0f, 0.0f};
            #pragma unroll
            for (int b = 0; b < 16; ++b) {
                T2c[b][m] = make_float2(p.r, p.i);
                p = cmul(p, Z);
            }
            const Cx z16 = p;            // dA^512
            // U rows for THIS half: start = dC * Z16^(4*half)
            const float Br = dt * denr * inv;
            const float Bi = -dt * deni * inv;
            const float Cr = C_real[(h * NM + m) * 2 + 0];
            const float Ci = C_real[(h * NM + m) * 2 + 1];
            const Cx dC = { 2.0f * (Cr * Br - Ci * Bi),     // factor 2 baked in
                            2.0f * (Cr * Bi + Ci * Br) };
            Cx y = half ? cmul(dC, csq(csq(z16))) : dC;
            #pragma unroll
            for (int a = 0; a < 4; ++a) {
                Uc[a][m] = make_float2(y.r, y.i);
                y = cmul(y, z16);
            }
            // B rows v in [20,32)
            const Cx ta3 = cmul(ta2, d8);   // dA^24
            #pragma unroll
            for (int v = 20; v < 24; ++v)
                emitB(sBh, sBl, v, wcR, wcI, hw, cmul(ta2, tb[v - 16]));
            #pragma unroll
            for (int v = 24; v < 32; ++v)
                emitB(sBh, sBl, v, wcR, wcI, hw, cmul(ta3, tb[v - 24]));
        }
    }
    __syncthreads();

    // ---- Mainloop (byte-identical to R10): warp wid -> rows [64*half + 32*wid, +32)
    const int gid = lane >> 2;
    const int tig = lane & 3;

    float acc[2][4][4] = {};

    const float4* B4h = reinterpret_cast<const float4*>(sBh);
    const float4* B4l = reinterpret_cast<const float4*>(sBl);

    #pragma unroll
    for (int kq = 0; kq < 2; ++kq) {
        // modes for this thread: n0, n0+1, n0+8, n0+9
        const int n0 = 16 * kq + 2 * tig;

        const float4 tg01 = *reinterpret_cast<const float4*>(&T2c[gid][n0]);
        const float4 tg89 = *reinterpret_cast<const float4*>(&T2c[gid][n0 + 8]);
        const float4 th01 = *reinterpret_cast<const float4*>(&T2c[gid + 8][n0]);
        const float4 th89 = *reinterpret_cast<const float4*>(&T2c[gid + 8][n0 + 8]);
        const float tg_r[4] = { tg01.x, tg01.z, tg89.x, tg89.z };
        const float tg_i[4] = { tg01.y, tg01.w, tg89.y, tg89.w };
        const float th_r[4] = { th01.x, th01.z, th89.x, th89.z };
        const float th_i[4] = { th01.y, th01.w, th89.y, th89.w };

        // A fragments: [ksel(Re/Im)][hi/lo][mt][reg]
        uint32_t Af[2][2][2][4];
        #pragma unroll
        for (int mt = 0; mt < 2; ++mt) {
            const int aLoc = 2 * wid + mt;
            const float4 u01 = *reinterpret_cast<const float4*>(&Uc[aLoc][n0]);
            const float4 u89 = *reinterpret_cast<const float4*>(&Uc[aLoc][n0 + 8]);
            const float u_r[4] = { u01.x, u01.z, u89.x, u89.z };
            const float u_i[4] = { u01.y, u01.w, u89.y, u89.w };
            float pr0[4], pi0[4], pr1[4], pi1[4];
            #pragma unroll
            for (int j = 0; j < 4; ++j) {
                pr0[j] = u_r[j] * tg_r[j] - u_i[j] * tg_i[j];
                pi0[j] = u_r[j] * tg_i[j] + u_i[j] * tg_r[j];
                pr1[j] = u_r[j] * th_r[j] - u_i[j] * th_i[j];
                pi1[j] = u_r[j] * th_i[j] + u_i[j] * th_r[j];
            }
            #pragma unroll
            for (int cp = 0; cp < 2; ++cp) {
                const int j0 = cp * 2, j1 = cp * 2 + 1;
                Af[0][0][mt][cp * 2 + 0] = pack_hi16(pr0[j0], pr0[j1]);
                Af[0][0][mt][cp * 2 + 1] = pack_hi16(pr1[j0], pr1[j1]);
                Af[1][0][mt][cp * 2 + 0] = pack_hi16(pi0[j0], pi0[j1]);
                Af[1][0][mt][cp * 2 + 1] = pack_hi16(pi1[j0], pi1[j1]);
                const float d00 = pr0[j0] - __uint_as_float(__float_as_uint(pr0[j0]) & 0xFFFF0000u);
                const float d01 = pr0[j1] - __uint_as_float(__float_as_uint(pr0[j1]) & 0xFFFF0000u);
                const float d10 = pr1[j0] - __uint_as_float(__float_as_uint(pr1[j0]) & 0xFFFF0000u);
                const float d11 = pr1[j1] - __uint_as_float(__float_as_uint(pr1[j1]) & 0xFFFF0000u);
                Af[0][1][mt][cp * 2 + 0] = pack_hi16(d00, d01);
                Af[0][1][mt][cp * 2 + 1] = pack_hi16(d10, d11);
                const float e00 = pi0[j0] - __uint_as_float(__float_as_uint(pi0[j0]) & 0xFFFF0000u);
                const float e01 = pi0[j1] - __uint_as_float(__float_as_uint(pi0[j1]) & 0xFFFF0000u);
                const float e10 = pi1[j0] - __uint_as_float(__float_as_uint(pi1[j0]) & 0xFFFF0000u);
                const float e11 = pi1[j1] - __uint_as_float(__float_as_uint(pi1[j1]) & 0xFFFF0000u);
                Af[1][1][mt][cp * 2 + 0] = pack_hi16(e00, e01);
                Af[1][1][mt][cp * 2 + 1] = pack_hi16(e10, e11);
            }
        }

        // MMAs: ksel 0 -> ks=kq (Re cols), ksel 1 -> ks=kq+2 (Im cols)
        #pragma unroll
        for (int ksel = 0; ksel < 2; ++ksel) {
            const int ks = kq + 2 * ksel;
            const float4 bh0 = B4h[(ks * 2 + 0) * 32 + lane];
            const float4 bh1 = B4h[(ks * 2 + 1) * 32 + lane];
            const float4 bl0 = B4l[(ks * 2 + 0) * 32 + lane];
            const float4 bl1 = B4l[(ks * 2 + 1) * 32 + lane];
            const uint32_t* h0 = reinterpret_cast<const uint32_t*>(&bh0);
            const uint32_t* h1 = reinterpret_cast<const uint32_t*>(&bh1);
            const uint32_t* l0 = reinterpret_cast<const uint32_t*>(&bl0);
            const uint32_t* l1 = reinterpret_cast<const uint32_t*>(&bl1);
            #pragma unroll
            for (int mt = 0; mt < 2; ++mt) {
                const uint32_t* ah = Af[ksel][0][mt];
                const uint32_t* al = Af[ksel][1][mt];
                #pragma unroll
                for (int nt = 0; nt < 4; ++nt) {
                    mma16816(acc[mt][nt], ah[0], ah[1], ah[2], ah[3], h0[nt], h1[nt]); // Fh*Gh
                    mma16816(acc[mt][nt], ah[0], ah[1], ah[2], ah[3], l0[nt], l1[nt]); // Fh*Gl
                    mma16816(acc[mt][nt], al[0], al[1], al[2], al[3], h0[nt], h1[nt]); // Fl*Gh
                }
            }
        }
    }

    // ---- Epilogue
    float* __restrict__ o = out + (size_t)h * LL;
    const int r0 = 64 * half + 32 * wid;
    #pragma unroll
    for (int mt = 0; mt < 2; ++mt) {
        const int u0 = r0 + mt * 16 + gid;
        #pragma unroll
        for (int nt = 0; nt < 4; ++nt) {
            const int v = nt * 8 + tig * 2;
            *reinterpret_cast<float2*>(o + (size_t)u0 * 32 + v) =
                make_float2(acc[mt][nt][0], acc[mt][nt][1]);
            *reinterpret_cast<float2*>(o + (size_t)(u0 + 8) * 32 + v) =
                make_float2(acc[mt][nt][2], acc[mt][nt][3]);
        }
    }
}

extern "C" void kernel_launch(void* const* d_in, const int* in_sizes, int n_in,
                              void* d_out, int out_size) {
    const float* log_dt     = (const float*)d_in[0];
    const float* C_real     = (const float*)d_in[1];
    const float* log_A_real = (const float*)d_in[2];
    const float* A_imag     = (const float*)d_in[3];
    float* out = (float*)d_out;
    s4d_hmma_kernel<<<HN * 2, TPB>>>(log_dt, C_real, log_A_real, A_imag, out);
}